// round 12
// baseline (speedup 1.0000x reference)
#include <cuda_runtime.h>
#include <cuda_bf16.h>
#include <cstdint>

// ---------------- problem constants ----------------
#define B_SZ     2048
#define D_SZ     128
#define C_SZ     64
#define T_STEPS  300
#define HU       100
#define ROWS_TOTAL (B_SZ * T_STEPS)       // 614400
#define TILE_M   256
#define N_TILES  (ROWS_TOTAL / TILE_M)    // 2400
#define GRID     148
#define NTH      512

#define KP      112                        // padded hidden; col/row 100 = bias lane
#define BIAS_K  100
#define A_LD    120
#define W23_LD  120
#define W4_LD   136
#define W2_OFF  0
#define W3_OFF  (KP * W23_LD)
#define W4_OFF  (2 * KP * W23_LD)
#define W_TOTAL (2 * KP * W23_LD + KP * W4_LD)            // 42112 b16
#define SMEM_MAIN (2 * TILE_M * A_LD * 2 + W_TOTAL * 2)   // 207104 B

// ---------------- device globals ----------------
__device__ __align__(16) __nv_bfloat16 g_Pb[B_SZ * KP];
__device__ __align__(16) __nv_bfloat16 g_Qb[B_SZ * KP];
__device__ float g_F[B_SZ];

// ---------------- mma helpers ----------------
__device__ __forceinline__ uint32_t smem_u32(const void* p) {
    return (uint32_t)__cvta_generic_to_shared(p);
}
__device__ __forceinline__ void ldm_x4(uint32_t addr, uint32_t& r0, uint32_t& r1,
                                       uint32_t& r2, uint32_t& r3) {
    asm volatile("ldmatrix.sync.aligned.m8n8.x4.shared.b16 {%0,%1,%2,%3}, [%4];"
                 : "=r"(r0), "=r"(r1), "=r"(r2), "=r"(r3) : "r"(addr));
}
__device__ __forceinline__ void ldm_x4_t(uint32_t addr, uint32_t& r0, uint32_t& r1,
                                         uint32_t& r2, uint32_t& r3) {
    asm volatile("ldmatrix.sync.aligned.m8n8.x4.trans.shared.b16 {%0,%1,%2,%3}, [%4];"
                 : "=r"(r0), "=r"(r1), "=r"(r2), "=r"(r3) : "r"(addr));
}
__device__ __forceinline__ void mma_bf16(float c[4], uint32_t a0, uint32_t a1, uint32_t a2,
                                         uint32_t a3, uint32_t b0, uint32_t b1) {
    asm volatile(
        "mma.sync.aligned.m16n8k16.row.col.f32.bf16.bf16.f32 "
        "{%0,%1,%2,%3},{%4,%5,%6,%7},{%8,%9},{%0,%1,%2,%3};"
        : "+f"(c[0]), "+f"(c[1]), "+f"(c[2]), "+f"(c[3])
        : "r"(a0), "r"(a1), "r"(a2), "r"(a3), "r"(b0), "r"(b1));
}
__device__ __forceinline__ void barpair(int mw) {
    asm volatile("bar.sync %0, 64;" :: "r"(mw + 1) : "memory");
}

// Asymmetric-width GEMM: NT n-tiles (8 cols each) starting at column colbase.
template<int NT, int BLD>
__device__ __forceinline__ void gemm_nt(const uint16_t* aS, const uint16_t* wS,
                                        int mw, int colbase, int lane,
                                        float acc[2][8][4])
{
    #pragma unroll
    for (int mt = 0; mt < 2; mt++)
        #pragma unroll
        for (int nt = 0; nt < NT; nt++)
            #pragma unroll
            for (int i = 0; i < 4; i++) acc[mt][nt][i] = 0.f;

    int l16 = lane & 15, lh = lane >> 4;
    #pragma unroll
    for (int kk = 0; kk < 7; kk++) {
        int ks = kk * 16;
        uint32_t a[2][4];
        #pragma unroll
        for (int mt = 0; mt < 2; mt++) {
            const uint16_t* p = aS + (mw * 32 + mt * 16 + l16) * A_LD + ks + 8 * lh;
            ldm_x4(smem_u32(p), a[mt][0], a[mt][1], a[mt][2], a[mt][3]);
        }
        uint32_t b[8][2];
        #pragma unroll
        for (int np = 0; np < (NT + 1) / 2; np++) {
            const uint16_t* p = wS + (ks + l16) * BLD + colbase + np * 16 + 8 * lh;
            uint32_t r0, r1, r2, r3;
            ldm_x4_t(smem_u32(p), r0, r1, r2, r3);
            b[np * 2][0] = r0;     b[np * 2][1] = r1;
            b[np * 2 + 1][0] = r2; b[np * 2 + 1][1] = r3;
        }
        #pragma unroll
        for (int mt = 0; mt < 2; mt++)
            #pragma unroll
            for (int nt = 0; nt < NT; nt++)
                mma_bf16(acc[mt][nt], a[mt][0], a[mt][1], a[mt][2], a[mt][3],
                         b[nt][0], b[nt][1]);
    }
}

template<int NT>
__device__ __forceinline__ void epi_nt(float acc[2][8][4],
                                       uint16_t* outS, int mw, int colbase, int lane)
{
    int qrow = lane >> 2, qcol = (lane & 3) * 2;
    #pragma unroll
    for (int mt = 0; mt < 2; mt++) {
        int r = mw * 32 + mt * 16 + qrow;
        #pragma unroll
        for (int nt = 0; nt < NT; nt++) {
            int c = colbase + nt * 8 + qcol;
            float v0 = fmaxf(acc[mt][nt][0], 0.f);
            float v1 = fmaxf(acc[mt][nt][1], 0.f);
            float v2 = fmaxf(acc[mt][nt][2], 0.f);
            float v3 = fmaxf(acc[mt][nt][3], 0.f);
            __nv_bfloat162 h0 = __floats2bfloat162_rn(v0, v1);
            __nv_bfloat162 h1 = __floats2bfloat162_rn(v2, v3);
            *(uint32_t*)(outS + r * A_LD + c)       = *(uint32_t*)&h0;
            *(uint32_t*)(outS + (r + 8) * A_LD + c) = *(uint32_t*)&h1;
        }
    }
}

// ---------------- prep v6: split-K chains, 512 CTAs x 512 thr ----------------
// Serial chain: L1(K=128) -> L2(K=100 split) -> L3(K=100 split) -> Q(K=64).
// P runs concurrently with L1; P-combine overlaps L2.
__global__ void __launch_bounds__(512)
prep_all(const float* __restrict__ x,
         const float* __restrict__ W1, const float* __restrict__ b1,
         const float* __restrict__ W2, const float* __restrict__ b2,
         const float* __restrict__ W3, const float* __restrict__ b3,
         const float* __restrict__ U1, const float* __restrict__ c1)
{
    __shared__ float sx[4][132];
    __shared__ float sa[4][204];
    __shared__ float sb[4][204];
    __shared__ float sh[4][68];
    __shared__ float Ppart[2 * 4 * 100];   // [kh][r][n]
    __shared__ float Bpart[2 * 4 * 200];
    __shared__ float Cpart[2 * 4 * 64];
    int tid = threadIdx.x;
    int m0 = blockIdx.x * 4;

    {
        int i = tid;                       // 4*128 = 512 exactly
        sx[i >> 7][i & 127] = __ldg(x + m0 * D_SZ + i);
    }
    if (tid < 4) g_F[m0 + tid] = 0.f;
    __syncthreads();

    // ---- phase A: L1 (0..199, K=128) || P split-K (256..455) || P-pad (456..467) ----
    if (tid < 200) {
        int n = tid;
        float accA[4] = {}, accB[4] = {};
        #pragma unroll 4
        for (int k = 0; k < 128; k += 4) {
            float w0 = __ldg(W1 + k * 200 + n);
            float w1 = __ldg(W1 + (k + 1) * 200 + n);
            float w2 = __ldg(W1 + (k + 2) * 200 + n);
            float w3 = __ldg(W1 + (k + 3) * 200 + n);
            #pragma unroll
            for (int r = 0; r < 4; r++) {
                accA[r] = fmaf(sx[r][k], w0, accA[r]);
                accB[r] = fmaf(sx[r][k + 1], w1, accB[r]);
                accA[r] = fmaf(sx[r][k + 2], w2, accA[r]);
                accB[r] = fmaf(sx[r][k + 3], w3, accB[r]);
            }
        }
        float bb = __ldg(b1 + n);
        #pragma unroll
        for (int r = 0; r < 4; r++) sa[r][n] = fmaxf(accA[r] + accB[r] + bb, 0.f);
    } else if (tid >= 256 && tid < 456) {
        int i = tid - 256;
        int kh = i / 100, n = i - kh * 100;
        int k0 = kh * 64;
        float accA[4] = {}, accB[4] = {};
        #pragma unroll 4
        for (int kk = 0; kk < 64; kk += 4) {
            int k = k0 + kk;
            float w0 = __ldg(U1 + k * HU + n);
            float w1 = __ldg(U1 + (k + 1) * HU + n);
            float w2 = __ldg(U1 + (k + 2) * HU + n);
            float w3 = __ldg(U1 + (k + 3) * HU + n);
            #pragma unroll
            for (int r = 0; r < 4; r++) {
                accA[r] = fmaf(sx[r][k], w0, accA[r]);
                accB[r] = fmaf(sx[r][k + 1], w1, accB[r]);
                accA[r] = fmaf(sx[r][k + 2], w2, accA[r]);
                accB[r] = fmaf(sx[r][k + 3], w3, accB[r]);
            }
        }
        #pragma unroll
        for (int r = 0; r < 4; r++)
            Ppart[kh * 400 + r * 100 + n] = accA[r] + accB[r];
    } else if (tid >= 456 && tid < 468) {
        int c = tid - 456 + 100;           // 100..111
        #pragma unroll
        for (int r = 0; r < 4; r++)
            g_Pb[(m0 + r) * KP + c] = __float2bfloat16(0.f);
    }
    __syncthreads();

    // ---- phase B: L2 split-K (0..399) || P combine (400..499) ----
    if (tid < 400) {
        int kh = tid / 200, n = tid - kh * 200;
        int k0 = kh * 100;
        float accA[4] = {}, accB[4] = {};
        #pragma unroll 4
        for (int kk = 0; kk < 100; kk += 4) {
            int k = k0 + kk;
            float w0 = __ldg(W2 + k * 200 + n);
            float w1 = __ldg(W2 + (k + 1) * 200 + n);
            float w2 = __ldg(W2 + (k + 2) * 200 + n);
            float w3 = __ldg(W2 + (k + 3) * 200 + n);
            #pragma unroll
            for (int r = 0; r < 4; r++) {
                accA[r] = fmaf(sa[r][k], w0, accA[r]);
                accB[r] = fmaf(sa[r][k + 1], w1, accB[r]);
                accA[r] = fmaf(sa[r][k + 2], w2, accA[r]);
                accB[r] = fmaf(sa[r][k + 3], w3, accB[r]);
            }
        }
        #pragma unroll
        for (int r = 0; r < 4; r++)
            Bpart[kh * 800 + r * 200 + n] = accA[r] + accB[r];
    } else if (tid < 500) {
        int n = tid - 400;
        #pragma unroll
        for (int r = 0; r < 4; r++)
            g_Pb[(m0 + r) * KP + n] =
                __float2bfloat16(Ppart[r * 100 + n] + Ppart[400 + r * 100 + n]);
    }
    __syncthreads();

    // ---- phase B2: combine L2 -> sb (relu + bias) ----
    if (tid < 200) {
        int n = tid;
        float bb = __ldg(b2 + n);
        #pragma unroll
        for (int r = 0; r < 4; r++)
            sb[r][n] = fmaxf(Bpart[r * 200 + n] + Bpart[800 + r * 200 + n] + bb, 0.f);
    }
    __syncthreads();

    // ---- phase C: L3 split-K (all 512) ----
    {
        int n = tid & 63, r = (tid >> 6) & 3, kh = tid >> 8;
        int k0 = kh * 100;
        float a0 = 0.f, a1 = 0.f, a2 = 0.f, a3 = 0.f;
        const float* ar = sb[r];
        #pragma unroll 4
        for (int kk = 0; kk < 100; kk += 4) {
            int k = k0 + kk;
            a0 = fmaf(ar[k],     __ldg(W3 + k * C_SZ + n), a0);
            a1 = fmaf(ar[k + 1], __ldg(W3 + (k + 1) * C_SZ + n), a1);
            a2 = fmaf(ar[k + 2], __ldg(W3 + (k + 2) * C_SZ + n), a2);
            a3 = fmaf(ar[k + 3], __ldg(W3 + (k + 3) * C_SZ + n), a3);
        }
        Cpart[kh * 256 + r * 64 + n] = (a0 + a1) + (a2 + a3);
    }
    __syncthreads();

    // ---- phase C2: combine L3 -> sh ----
    if (tid < 256) {
        int n = tid & 63, r = tid >> 6;
        sh[r][n] = fmaxf(Cpart[r * 64 + n] + Cpart[256 + r * 64 + n] + __ldg(b3 + n), 0.f);
    }
    __syncthreads();

    // ---- phase D: Q (0..99, K=64) + pad (100..111) ----
    if (tid < 100) {
        int n = tid;
        const float* Uq = U1 + D_SZ * HU;
        float accA[4] = {}, accB[4] = {};
        #pragma unroll 4
        for (int k = 0; k < 64; k += 4) {
            float w0 = __ldg(Uq + k * HU + n);
            float w1 = __ldg(Uq + (k + 1) * HU + n);
            float w2 = __ldg(Uq + (k + 2) * HU + n);
            float w3 = __ldg(Uq + (k + 3) * HU + n);
            #pragma unroll
            for (int r = 0; r < 4; r++) {
                accA[r] = fmaf(sh[r][k], w0, accA[r]);
                accB[r] = fmaf(sh[r][k + 1], w1, accB[r]);
                accA[r] = fmaf(sh[r][k + 2], w2, accA[r]);
                accB[r] = fmaf(sh[r][k + 3], w3, accB[r]);
            }
        }
        float cc = __ldg(c1 + n);
        #pragma unroll
        for (int r = 0; r < 4; r++)
            g_Qb[(m0 + r) * KP + n] = __float2bfloat16(accA[r] + accB[r] + cc);
    } else if (tid < 112) {
        float v = (tid == BIAS_K) ? 1.0f : 0.0f;
        #pragma unroll
        for (int r = 0; r < 4; r++)
            g_Qb[(m0 + r) * KP + tid] = __float2bfloat16(v);
    }
}

// ---------------- main: persistent bf16 mma kernel (R10, no prefetch) ----------
__global__ void __launch_bounds__(NTH, 1)
umnn_main(const float* __restrict__ x,
          const float* __restrict__ U2, const float* __restrict__ c2,
          const float* __restrict__ U3, const float* __restrict__ c3,
          const float* __restrict__ U4, const float* __restrict__ c4)
{
    extern __shared__ __align__(16) uint16_t sm[];
    uint16_t* As1 = sm;
    uint16_t* As2 = sm + TILE_M * A_LD;
    uint16_t* Wsm = sm + 2 * TILE_M * A_LD;

    int tid = threadIdx.x;
    int lane = tid & 31, w = tid >> 5;
    int mw = w & 7, nw = w >> 3;

    // zero activation buffers (unwritten cols stay 0 forever; avoids NaN*0)
    for (int i = tid; i < 2 * TILE_M * A_LD; i += NTH) sm[i] = 0;

    // pack weights with bias folded into k-row BIAS_K
    for (int i = tid; i < KP * W23_LD; i += NTH) {
        int k = i / W23_LD, n = i - k * W23_LD;
        float a = 0.f, b = 0.f;
        if (k < HU && n < HU) {
            a = __ldg(U2 + k * HU + n);
            b = __ldg(U3 + k * HU + n);
        } else if (k == BIAS_K) {
            if (n < HU)            { a = __ldg(c2 + n); b = __ldg(c3 + n); }
            else if (n == BIAS_K)  { a = 1.0f;          b = 1.0f; }
        }
        __nv_bfloat16 ha = __float2bfloat16(a), hb = __float2bfloat16(b);
        Wsm[W2_OFF + i] = *(uint16_t*)&ha;
        Wsm[W3_OFF + i] = *(uint16_t*)&hb;
    }
    for (int i = tid; i < KP * W4_LD; i += NTH) {
        int k = i / W4_LD, n = i - k * W4_LD;
        float a = 0.f;
        if (k < HU && n < D_SZ)            a = __ldg(U4 + k * D_SZ + n);
        else if (k == BIAS_K && n < D_SZ)  a = __ldg(c4 + n);
        __nv_bfloat16 ha = __float2bfloat16(a);
        Wsm[W4_OFF + i] = *(uint16_t*)&ha;
    }
    __syncthreads();

    const uint16_t* W2s = Wsm + W2_OFF;
    const uint16_t* W3s = Wsm + W3_OFF;
    const uint16_t* W4s = Wsm + W4_OFF;

    int sl = nw * 32 + lane;
    int blr = sl >> 1, bhalf = sl & 1;
    int qrow = lane >> 2, qcol = (lane & 3) * 2;

    float acc[2][8][4];

    for (int tile = blockIdx.x; tile < N_TILES; tile += GRID) {
        int r0 = tile * TILE_M;
        int b0 = r0 / T_STEPS;
        int split = (b0 + 1) * T_STEPS - r0;

        barpair(mw);

        // build A1 = bf16(relu(t*P[b] + Q[b])) (col BIAS_K -> 1)
        {
            int row = mw * 32 + blr;
            int r = r0 + row;
            int b = r / T_STEPS;
            float tv = ((float)(r - b * T_STEPS) + 0.5f) * (1.0f / T_STEPS);
            const uint4* Pp = (const uint4*)(g_Pb + b * KP + bhalf * 56);
            const uint4* Qp = (const uint4*)(g_Qb + b * KP + bhalf * 56);
            uint4* dst = (uint4*)(As1 + row * A_LD + bhalf * 56);
            #pragma unroll
            for (int j = 0; j < 7; j++) {
                uint4 pv = __ldg(Pp + j);
                uint4 qv = __ldg(Qp + j);
                uint32_t pw[4] = {pv.x, pv.y, pv.z, pv.w};
                uint32_t qw[4] = {qv.x, qv.y, qv.z, qv.w};
                uint32_t ow[4];
                #pragma unroll
                for (int u = 0; u < 4; u++) {
                    float2 p2 = __bfloat1622float2(*(__nv_bfloat162*)&pw[u]);
                    float2 q2 = __bfloat1622float2(*(__nv_bfloat162*)&qw[u]);
                    float v0 = fmaxf(fmaf(tv, p2.x, q2.x), 0.f);
                    float v1 = fmaxf(fmaf(tv, p2.y, q2.y), 0.f);
                    __nv_bfloat162 h = __floats2bfloat162_rn(v0, v1);
                    ow[u] = *(uint32_t*)&h;
                }
                dst[j] = make_uint4(ow[0], ow[1], ow[2], ow[3]);
            }
        }
        barpair(mw);

        // L2 (13 n-tiles: nw0 -> 7 @0, nw1 -> 6 @56)
        if (nw == 0) {
            gemm_nt<7, W23_LD>(As1, W2s, mw, 0, lane, acc);
            epi_nt<7>(acc, As2, mw, 0, lane);
        } else {
            gemm_nt<6, W23_LD>(As1, W2s, mw, 56, lane, acc);
            epi_nt<6>(acc, As2, mw, 56, lane);
        }
        barpair(mw);

        // L3
        if (nw == 0) {
            gemm_nt<7, W23_LD>(As2, W3s, mw, 0, lane, acc);
            epi_nt<7>(acc, As1, mw, 0, lane);
        } else {
            gemm_nt<6, W23_LD>(As2, W3s, mw, 56, lane, acc);
            epi_nt<6>(acc, As1, mw, 56, lane);
        }
        barpair(mw);

        // L4 (full 16 n-tiles: 8 per warp) + quadrature dot
        gemm_nt<8, W4_LD>(As1, W4s, mw, nw * 64, lane, acc);
        {
            #pragma unroll
            for (int mt = 0; mt < 2; mt++) {
                int rA = mw * 32 + mt * 16 + qrow;
                int rB = rA + 8;
                int bA = b0 + (rA >= split);
                int bB = b0 + (rB >= split);
                const float* xA = x + bA * D_SZ;
                const float* xB = x + bB * D_SZ;
                float sA = 0.f, sB = 0.f;
                #pragma unroll
                for (int nt = 0; nt < 8; nt++) {
                    int c = nw * 64 + nt * 8 + qcol;
                    float p0 = acc[mt][nt][0], p1 = acc[mt][nt][1];
                    float p2 = acc[mt][nt][2], p3 = acc[mt][nt][3];
                    float f0 = p0 > 0.f ? p0 + 1.f : __expf(p0);
                    float f1 = p1 > 0.f ? p1 + 1.f : __expf(p1);
                    float f2 = p2 > 0.f ? p2 + 1.f : __expf(p2);
                    float f3 = p3 > 0.f ? p3 + 1.f : __expf(p3);
                    sA += f0 * __ldg(xA + c) + f1 * __ldg(xA + c + 1);
                    sB += f2 * __ldg(xB + c) + f3 * __ldg(xB + c + 1);
                }
                sA += __shfl_xor_sync(0xffffffff, sA, 1);
                sA += __shfl_xor_sync(0xffffffff, sA, 2);
                sB += __shfl_xor_sync(0xffffffff, sB, 1);
                sB += __shfl_xor_sync(0xffffffff, sB, 2);
                if ((lane & 3) == 0) {
                    atomicAdd(&g_F[bA], sA);
                    atomicAdd(&g_F[bB], sB);
                }
            }
        }
    }
}

// ---------------- finish: sigmoid(F / T) ----------------
__global__ void finish_kernel(float* __restrict__ out)
{
    int i = blockIdx.x * blockDim.x + threadIdx.x;
    if (i < B_SZ) {
        float F = g_F[i] * (1.0f / T_STEPS);
        out[i] = 1.0f / (1.0f + expf(-F));
    }
}

// ---------------- launch ----------------
extern "C" void kernel_launch(void* const* d_in, const int* in_sizes, int n_in,
                              void* d_out, int out_size)
{
    (void)in_sizes; (void)n_in; (void)out_size;
    const float* x  = (const float*)d_in[0];
    const float* W1 = (const float*)d_in[1];
    const float* b1 = (const float*)d_in[2];
    const float* W2 = (const float*)d_in[3];
    const float* b2 = (const float*)d_in[4];
    const float* W3 = (const float*)d_in[5];
    const float* b3 = (const float*)d_in[6];
    const float* U1 = (const float*)d_in[7];
    const float* c1 = (const float*)d_in[8];
    const float* U2 = (const float*)d_in[9];
    const float* c2 = (const float*)d_in[10];
    const float* U3 = (const float*)d_in[11];
    const float* c3 = (const float*)d_in[12];
    const float* U4 = (const float*)d_in[13];
    const float* c4 = (const float*)d_in[14];
    float* out = (float*)d_out;

    cudaFuncSetAttribute(umnn_main, cudaFuncAttributeMaxDynamicSharedMemorySize, SMEM_MAIN);

    // 1) prep v6: split-K chains (512 CTAs x 512 thr)
    prep_all<<<512, 512>>>(x, W1, b1, W2, b2, W3, b3, U1, c1);
    // 2) persistent bf16 mma main kernel (R10 config)
    umnn_main<<<GRID, NTH, SMEM_MAIN>>>(x, U2, c2, U3, c3, U4, c4);
    // 3) out = sigmoid(F / 300)
    finish_kernel<<<(B_SZ + 255) / 256, 256>>>(out);
}

// round 13
// speedup vs baseline: 1.3647x; 1.3647x over previous
#include <cuda_runtime.h>
#include <cuda_bf16.h>
#include <cstdint>

// ---------------- problem constants ----------------
#define B_SZ     2048
#define D_SZ     128
#define C_SZ     64
#define T_STEPS  300
#define HU       100
#define ROWS_TOTAL (B_SZ * T_STEPS)       // 614400
#define GRID     148
#define NTH      512
#define NCHUNK   (ROWS_TOTAL / 16)        // 38400 16-row chunks
#define GW_STRIDE (GRID * 16)             // 2368 global warps

#define KP      112                        // padded hidden; col/row 100 = bias lane
#define BIAS_K  100
#define W23_LD  120
#define W4_LD   136
#define W2_OFF  0
#define W3_OFF  (KP * W23_LD)
#define W4_OFF  (2 * KP * W23_LD)
#define W_TOTAL (2 * KP * W23_LD + KP * W4_LD)   // 42112 b16
#define SMEM_MAIN (W_TOTAL * 2)                  // 84224 B (weights only!)

// ---------------- device globals ----------------
__device__ __align__(16) __nv_bfloat16 g_Pb[B_SZ * KP];
__device__ __align__(16) __nv_bfloat16 g_Qb[B_SZ * KP];
__device__ float g_F[B_SZ];

// ---------------- helpers ----------------
__device__ __forceinline__ uint32_t smem_u32(const void* p) {
    return (uint32_t)__cvta_generic_to_shared(p);
}
__device__ __forceinline__ void ldm_x4_t(uint32_t addr, uint32_t& r0, uint32_t& r1,
                                         uint32_t& r2, uint32_t& r3) {
    asm volatile("ldmatrix.sync.aligned.m8n8.x4.trans.shared.b16 {%0,%1,%2,%3}, [%4];"
                 : "=r"(r0), "=r"(r1), "=r"(r2), "=r"(r3) : "r"(addr));
}
__device__ __forceinline__ void mma_bf16(float c[4], uint32_t a0, uint32_t a1, uint32_t a2,
                                         uint32_t a3, uint32_t b0, uint32_t b1) {
    asm volatile(
        "mma.sync.aligned.m16n8k16.row.col.f32.bf16.bf16.f32 "
        "{%0,%1,%2,%3},{%4,%5,%6,%7},{%8,%9},{%0,%1,%2,%3};"
        : "+f"(c[0]), "+f"(c[1]), "+f"(c[2]), "+f"(c[3])
        : "r"(a0), "r"(a1), "r"(a2), "r"(a3), "r"(b0), "r"(b1));
}
__device__ __forceinline__ uint32_t pack_relu2(float v0, float v1) {
    __nv_bfloat162 h = __floats2bfloat162_rn(fmaxf(v0, 0.f), fmaxf(v1, 0.f));
    return *(uint32_t*)&h;
}
// build one A-fragment reg: bf16x2 of relu(t*P[k..k+1] + Q[k..k+1])
__device__ __forceinline__ uint32_t bpair(const uint16_t* P, const uint16_t* Q,
                                          int k, float tv) {
    uint32_t pu = __ldg((const uint32_t*)(P + k));
    uint32_t qu = __ldg((const uint32_t*)(Q + k));
    float2 p2 = __bfloat1622float2(*(__nv_bfloat162*)&pu);
    float2 q2 = __bfloat1622float2(*(__nv_bfloat162*)&qu);
    return pack_relu2(fmaf(tv, p2.x, q2.x), fmaf(tv, p2.y, q2.y));
}

// NT n-tiles (8 cols each) chained GEMM: A from register fragments, B from smem.
template<int NT, int BLD>
__device__ __forceinline__ void gemm_chain(const uint32_t af[7][4], const uint16_t* wS,
                                           int l16, int lh, float acc[NT][4])
{
    #pragma unroll
    for (int nt = 0; nt < NT; nt++)
        #pragma unroll
        for (int i = 0; i < 4; i++) acc[nt][i] = 0.f;

    #pragma unroll
    for (int kk = 0; kk < 7; kk++) {
        const uint16_t* wrow = wS + (kk * 16 + l16) * BLD + 8 * lh;
        #pragma unroll
        for (int np = 0; np < NT / 2; np++) {
            uint32_t r0, r1, r2, r3;
            ldm_x4_t(smem_u32(wrow + np * 16), r0, r1, r2, r3);
            mma_bf16(acc[2 * np],     af[kk][0], af[kk][1], af[kk][2], af[kk][3], r0, r1);
            mma_bf16(acc[2 * np + 1], af[kk][0], af[kk][1], af[kk][2], af[kk][3], r2, r3);
        }
    }
}

// C-fragment (14 n-tiles) -> next-layer A-fragment, relu+bf16, pure registers
__device__ __forceinline__ void repack(const float acc[14][4], uint32_t af[7][4])
{
    #pragma unroll
    for (int j = 0; j < 7; j++) {
        af[j][0] = pack_relu2(acc[2 * j][0],     acc[2 * j][1]);
        af[j][1] = pack_relu2(acc[2 * j][2],     acc[2 * j][3]);
        af[j][2] = pack_relu2(acc[2 * j + 1][0], acc[2 * j + 1][1]);
        af[j][3] = pack_relu2(acc[2 * j + 1][2], acc[2 * j + 1][3]);
    }
}

// ---------------- prep v6: split-K chains, 512 CTAs x 512 thr (R12, measured 59.5us) --
__global__ void __launch_bounds__(512)
prep_all(const float* __restrict__ x,
         const float* __restrict__ W1, const float* __restrict__ b1,
         const float* __restrict__ W2, const float* __restrict__ b2,
         const float* __restrict__ W3, const float* __restrict__ b3,
         const float* __restrict__ U1, const float* __restrict__ c1)
{
    __shared__ float sx[4][132];
    __shared__ float sa[4][204];
    __shared__ float sb[4][204];
    __shared__ float sh[4][68];
    __shared__ float Ppart[2 * 4 * 100];
    __shared__ float Bpart[2 * 4 * 200];
    __shared__ float Cpart[2 * 4 * 64];
    int tid = threadIdx.x;
    int m0 = blockIdx.x * 4;

    {
        int i = tid;
        sx[i >> 7][i & 127] = __ldg(x + m0 * D_SZ + i);
    }
    if (tid < 4) g_F[m0 + tid] = 0.f;
    __syncthreads();

    if (tid < 200) {
        int n = tid;
        float accA[4] = {}, accB[4] = {};
        #pragma unroll 4
        for (int k = 0; k < 128; k += 4) {
            float w0 = __ldg(W1 + k * 200 + n);
            float w1 = __ldg(W1 + (k + 1) * 200 + n);
            float w2 = __ldg(W1 + (k + 2) * 200 + n);
            float w3 = __ldg(W1 + (k + 3) * 200 + n);
            #pragma unroll
            for (int r = 0; r < 4; r++) {
                accA[r] = fmaf(sx[r][k], w0, accA[r]);
                accB[r] = fmaf(sx[r][k + 1], w1, accB[r]);
                accA[r] = fmaf(sx[r][k + 2], w2, accA[r]);
                accB[r] = fmaf(sx[r][k + 3], w3, accB[r]);
            }
        }
        float bb = __ldg(b1 + n);
        #pragma unroll
        for (int r = 0; r < 4; r++) sa[r][n] = fmaxf(accA[r] + accB[r] + bb, 0.f);
    } else if (tid >= 256 && tid < 456) {
        int i = tid - 256;
        int kh = i / 100, n = i - kh * 100;
        int k0 = kh * 64;
        float accA[4] = {}, accB[4] = {};
        #pragma unroll 4
        for (int kk = 0; kk < 64; kk += 4) {
            int k = k0 + kk;
            float w0 = __ldg(U1 + k * HU + n);
            float w1 = __ldg(U1 + (k + 1) * HU + n);
            float w2 = __ldg(U1 + (k + 2) * HU + n);
            float w3 = __ldg(U1 + (k + 3) * HU + n);
            #pragma unroll
            for (int r = 0; r < 4; r++) {
                accA[r] = fmaf(sx[r][k], w0, accA[r]);
                accB[r] = fmaf(sx[r][k + 1], w1, accB[r]);
                accA[r] = fmaf(sx[r][k + 2], w2, accA[r]);
                accB[r] = fmaf(sx[r][k + 3], w3, accB[r]);
            }
        }
        #pragma unroll
        for (int r = 0; r < 4; r++)
            Ppart[kh * 400 + r * 100 + n] = accA[r] + accB[r];
    } else if (tid >= 456 && tid < 468) {
        int c = tid - 456 + 100;
        #pragma unroll
        for (int r = 0; r < 4; r++)
            g_Pb[(m0 + r) * KP + c] = __float2bfloat16(0.f);
    }
    __syncthreads();

    if (tid < 400) {
        int kh = tid / 200, n = tid - kh * 200;
        int k0 = kh * 100;
        float accA[4] = {}, accB[4] = {};
        #pragma unroll 4
        for (int kk = 0; kk < 100; kk += 4) {
            int k = k0 + kk;
            float w0 = __ldg(W2 + k * 200 + n);
            float w1 = __ldg(W2 + (k + 1) * 200 + n);
            float w2 = __ldg(W2 + (k + 2) * 200 + n);
            float w3 = __ldg(W2 + (k + 3) * 200 + n);
            #pragma unroll
            for (int r = 0; r < 4; r++) {
                accA[r] = fmaf(sa[r][k], w0, accA[r]);
                accB[r] = fmaf(sa[r][k + 1], w1, accB[r]);
                accA[r] = fmaf(sa[r][k + 2], w2, accA[r]);
                accB[r] = fmaf(sa[r][k + 3], w3, accB[r]);
            }
        }
        #pragma unroll
        for (int r = 0; r < 4; r++)
            Bpart[kh * 800 + r * 200 + n] = accA[r] + accB[r];
    } else if (tid < 500) {
        int n = tid - 400;
        #pragma unroll
        for (int r = 0; r < 4; r++)
            g_Pb[(m0 + r) * KP + n] =
                __float2bfloat16(Ppart[r * 100 + n] + Ppart[400 + r * 100 + n]);
    }
    __syncthreads();

    if (tid < 200) {
        int n = tid;
        float bb = __ldg(b2 + n);
        #pragma unroll
        for (int r = 0; r < 4; r++)
            sb[r][n] = fmaxf(Bpart[r * 200 + n] + Bpart[800 + r * 200 + n] + bb, 0.f);
    }
    __syncthreads();

    {
        int n = tid & 63, r = (tid >> 6) & 3, kh = tid >> 8;
        int k0 = kh * 100;
        float a0 = 0.f, a1 = 0.f, a2 = 0.f, a3 = 0.f;
        const float* ar = sb[r];
        #pragma unroll 4
        for (int kk = 0; kk < 100; kk += 4) {
            int k = k0 + kk;
            a0 = fmaf(ar[k],     __ldg(W3 + k * C_SZ + n), a0);
            a1 = fmaf(ar[k + 1], __ldg(W3 + (k + 1) * C_SZ + n), a1);
            a2 = fmaf(ar[k + 2], __ldg(W3 + (k + 2) * C_SZ + n), a2);
            a3 = fmaf(ar[k + 3], __ldg(W3 + (k + 3) * C_SZ + n), a3);
        }
        Cpart[kh * 256 + r * 64 + n] = (a0 + a1) + (a2 + a3);
    }
    __syncthreads();

    if (tid < 256) {
        int n = tid & 63, r = tid >> 6;
        sh[r][n] = fmaxf(Cpart[r * 64 + n] + Cpart[256 + r * 64 + n] + __ldg(b3 + n), 0.f);
    }
    __syncthreads();

    if (tid < 100) {
        int n = tid;
        const float* Uq = U1 + D_SZ * HU;
        float accA[4] = {}, accB[4] = {};
        #pragma unroll 4
        for (int k = 0; k < 64; k += 4) {
            float w0 = __ldg(Uq + k * HU + n);
            float w1 = __ldg(Uq + (k + 1) * HU + n);
            float w2 = __ldg(Uq + (k + 2) * HU + n);
            float w3 = __ldg(Uq + (k + 3) * HU + n);
            #pragma unroll
            for (int r = 0; r < 4; r++) {
                accA[r] = fmaf(sh[r][k], w0, accA[r]);
                accB[r] = fmaf(sh[r][k + 1], w1, accB[r]);
                accA[r] = fmaf(sh[r][k + 2], w2, accA[r]);
                accB[r] = fmaf(sh[r][k + 3], w3, accB[r]);
            }
        }
        float cc = __ldg(c1 + n);
        #pragma unroll
        for (int r = 0; r < 4; r++)
            g_Qb[(m0 + r) * KP + n] = __float2bfloat16(accA[r] + accB[r] + cc);
    } else if (tid < 112) {
        float v = (tid == BIAS_K) ? 1.0f : 0.0f;
        #pragma unroll
        for (int r = 0; r < 4; r++)
            g_Qb[(m0 + r) * KP + tid] = __float2bfloat16(v);
    }
}

// ---------------- main: register-chained bf16 mma, barrier-free tile loop ---------
__global__ void __launch_bounds__(NTH, 1)
umnn_main(const float* __restrict__ x,
          const float* __restrict__ U2, const float* __restrict__ c2,
          const float* __restrict__ U3, const float* __restrict__ c3,
          const float* __restrict__ U4, const float* __restrict__ c4)
{
    extern __shared__ __align__(16) uint16_t Wsm[];
    int tid = threadIdx.x;

    // pack weights with bias folded into k-row BIAS_K (only CTA-wide sync here)
    for (int i = tid; i < KP * W23_LD; i += NTH) {
        int k = i / W23_LD, n = i - k * W23_LD;
        float a = 0.f, b = 0.f;
        if (k < HU && n < HU) {
            a = __ldg(U2 + k * HU + n);
            b = __ldg(U3 + k * HU + n);
        } else if (k == BIAS_K) {
            if (n < HU)            { a = __ldg(c2 + n); b = __ldg(c3 + n); }
            else if (n == BIAS_K)  { a = 1.0f;          b = 1.0f; }
        }
        __nv_bfloat16 ha = __float2bfloat16(a), hb = __float2bfloat16(b);
        Wsm[W2_OFF + i] = *(uint16_t*)&ha;
        Wsm[W3_OFF + i] = *(uint16_t*)&hb;
    }
    for (int i = tid; i < KP * W4_LD; i += NTH) {
        int k = i / W4_LD, n = i - k * W4_LD;
        float a = 0.f;
        if (k < HU && n < D_SZ)            a = __ldg(U4 + k * D_SZ + n);
        else if (k == BIAS_K && n < D_SZ)  a = __ldg(c4 + n);
        __nv_bfloat16 ha = __float2bfloat16(a);
        Wsm[W4_OFF + i] = *(uint16_t*)&ha;
    }
    __syncthreads();

    const uint16_t* W2s = Wsm + W2_OFF;
    const uint16_t* W3s = Wsm + W3_OFF;
    const uint16_t* W4s = Wsm + W4_OFF;

    int lane = tid & 31, w = tid >> 5;
    int tg = lane & 3, qrow = lane >> 2;
    int l16 = lane & 15, lh = lane >> 4;
    int gw = blockIdx.x * 16 + w;

    for (int chunk = gw; chunk < NCHUNK; chunk += GW_STRIDE) {
        int r0 = chunk * 16;
        int rA = r0 + qrow, rB = rA + 8;
        int bA = rA / T_STEPS, bB = rB / T_STEPS;
        float tA = ((float)(rA - bA * T_STEPS) + 0.5f) * (1.0f / T_STEPS);
        float tB = ((float)(rB - bB * T_STEPS) + 0.5f) * (1.0f / T_STEPS);
        const uint16_t* PA = (const uint16_t*)g_Pb + bA * KP;
        const uint16_t* QA = (const uint16_t*)g_Qb + bA * KP;
        const uint16_t* PB = (const uint16_t*)g_Pb + bB * KP;
        const uint16_t* QB = (const uint16_t*)g_Qb + bB * KP;

        // build A1 fragments directly in registers
        uint32_t af[7][4];
        #pragma unroll
        for (int j = 0; j < 7; j++) {
            int k0 = j * 16 + tg * 2;
            af[j][0] = bpair(PA, QA, k0,     tA);
            af[j][1] = bpair(PB, QB, k0,     tB);
            af[j][2] = bpair(PA, QA, k0 + 8, tA);
            af[j][3] = bpair(PB, QB, k0 + 8, tB);
        }

        // L2 -> L3 (register-chained, no smem, no sync)
        float acc[14][4];
        gemm_chain<14, W23_LD>(af, W2s, l16, lh, acc);
        repack(acc, af);
        gemm_chain<14, W23_LD>(af, W3s, l16, lh, acc);
        repack(acc, af);

        // L4 + quadrature dot
        float acc4[16][4];
        gemm_chain<16, W4_LD>(af, W4s, l16, lh, acc4);

        const float* xA = x + bA * D_SZ;
        const float* xB = x + bB * D_SZ;
        float sA = 0.f, sB = 0.f;
        #pragma unroll
        for (int nt = 0; nt < 16; nt++) {
            int c = nt * 8 + tg * 2;
            float p0 = acc4[nt][0], p1 = acc4[nt][1];
            float p2 = acc4[nt][2], p3 = acc4[nt][3];
            float f0 = p0 > 0.f ? p0 + 1.f : __expf(p0);
            float f1 = p1 > 0.f ? p1 + 1.f : __expf(p1);
            float f2 = p2 > 0.f ? p2 + 1.f : __expf(p2);
            float f3 = p3 > 0.f ? p3 + 1.f : __expf(p3);
            sA += f0 * __ldg(xA + c) + f1 * __ldg(xA + c + 1);
            sB += f2 * __ldg(xB + c) + f3 * __ldg(xB + c + 1);
        }
        sA += __shfl_xor_sync(0xffffffff, sA, 1);
        sA += __shfl_xor_sync(0xffffffff, sA, 2);
        sB += __shfl_xor_sync(0xffffffff, sB, 1);
        sB += __shfl_xor_sync(0xffffffff, sB, 2);
        if (tg == 0) {
            atomicAdd(&g_F[bA], sA);
            atomicAdd(&g_F[bB], sB);
        }
    }
}

// ---------------- finish: sigmoid(F / T) ----------------
__global__ void finish_kernel(float* __restrict__ out)
{
    int i = blockIdx.x * blockDim.x + threadIdx.x;
    if (i < B_SZ) {
        float F = g_F[i] * (1.0f / T_STEPS);
        out[i] = 1.0f / (1.0f + expf(-F));
    }
}

// ---------------- launch ----------------
extern "C" void kernel_launch(void* const* d_in, const int* in_sizes, int n_in,
                              void* d_out, int out_size)
{
    (void)in_sizes; (void)n_in; (void)out_size;
    const float* x  = (const float*)d_in[0];
    const float* W1 = (const float*)d_in[1];
    const float* b1 = (const float*)d_in[2];
    const float* W2 = (const float*)d_in[3];
    const float* b2 = (const float*)d_in[4];
    const float* W3 = (const float*)d_in[5];
    const float* b3 = (const float*)d_in[6];
    const float* U1 = (const float*)d_in[7];
    const float* c1 = (const float*)d_in[8];
    const float* U2 = (const float*)d_in[9];
    const float* c2 = (const float*)d_in[10];
    const float* U3 = (const float*)d_in[11];
    const float* c3 = (const float*)d_in[12];
    const float* U4 = (const float*)d_in[13];
    const float* c4 = (const float*)d_in[14];
    float* out = (float*)d_out;

    cudaFuncSetAttribute(umnn_main, cudaFuncAttributeMaxDynamicSharedMemorySize, SMEM_MAIN);

    // 1) prep v6 (R12, measured 59.5us)
    prep_all<<<512, 512>>>(x, W1, b1, W2, b2, W3, b3, U1, c1);
    // 2) register-chained persistent mma main kernel (barrier-free)
    umnn_main<<<GRID, NTH, SMEM_MAIN>>>(x, U2, c2, U3, c3, U4, c4);
    // 3) out = sigmoid(F / 300)
    finish_kernel<<<(B_SZ + 255) / 256, 256>>>(out);
}

// round 14
// speedup vs baseline: 1.4970x; 1.0969x over previous
#include <cuda_runtime.h>
#include <cuda_bf16.h>
#include <cstdint>

// ---------------- problem constants ----------------
#define B_SZ     2048
#define D_SZ     128
#define C_SZ     64
#define T_STEPS  300
#define HU       100
#define ROWS_TOTAL (B_SZ * T_STEPS)       // 614400
#define GRID     148
#define NTH      512
#define NCHUNK   (ROWS_TOTAL / 16)        // 38400
#define GW_STRIDE (GRID * 16)

#define KP      112                        // padded hidden; col/row 100 = bias lane
#define BIAS_K  100
#define W23_LD  120
#define W4_LD   136
#define W2_OFF  0
#define W3_OFF  (KP * W23_LD)
#define W4_OFF  (2 * KP * W23_LD)
#define W_TOTAL (2 * KP * W23_LD + KP * W4_LD)   // 42112 b16
#define SMEM_MAIN (W_TOTAL * 2)                  // 84224 B

// prep packed-weight layouts (bf16, [k][LD])
#define PBLD   216       // W1/W2 + activations row stride
#define P3LD   72        // W3
#define PULD   120       // U1 halves
#define W1P_N  (128 * PBLD)   // 27648
#define W2P_N  (208 * PBLD)   // 44928
#define W3P_N  (208 * P3LD)   // 14976
#define U1PP_N (128 * PULD)   // 15360
#define U1QP_N (64 * PULD)    // 7680
#define PREP_SMEM ((W2P_N + 2 * 16 * PBLD) * 2)  // 103680 B

// ---------------- device globals ----------------
__device__ __align__(16) __nv_bfloat16 g_Pb[B_SZ * KP];
__device__ __align__(16) __nv_bfloat16 g_Qb[B_SZ * KP];
__device__ float g_F[B_SZ];
__device__ __align__(16) uint16_t g_W1p[W1P_N];
__device__ __align__(16) uint16_t g_W2p[W2P_N];
__device__ __align__(16) uint16_t g_W3p[W3P_N];
__device__ __align__(16) uint16_t g_U1Pp[U1PP_N];
__device__ __align__(16) uint16_t g_U1Qp[U1QP_N];

// ---------------- helpers ----------------
__device__ __forceinline__ uint32_t smem_u32(const void* p) {
    return (uint32_t)__cvta_generic_to_shared(p);
}
__device__ __forceinline__ void ldm_x4_t(uint32_t addr, uint32_t& r0, uint32_t& r1,
                                         uint32_t& r2, uint32_t& r3) {
    asm volatile("ldmatrix.sync.aligned.m8n8.x4.trans.shared.b16 {%0,%1,%2,%3}, [%4];"
                 : "=r"(r0), "=r"(r1), "=r"(r2), "=r"(r3) : "r"(addr));
}
__device__ __forceinline__ void mma_bf16(float c[4], uint32_t a0, uint32_t a1, uint32_t a2,
                                         uint32_t a3, uint32_t b0, uint32_t b1) {
    asm volatile(
        "mma.sync.aligned.m16n8k16.row.col.f32.bf16.bf16.f32 "
        "{%0,%1,%2,%3},{%4,%5,%6,%7},{%8,%9},{%0,%1,%2,%3};"
        : "+f"(c[0]), "+f"(c[1]), "+f"(c[2]), "+f"(c[3])
        : "r"(a0), "r"(a1), "r"(a2), "r"(a3), "r"(b0), "r"(b1));
}
__device__ __forceinline__ uint32_t pack_relu2(float v0, float v1) {
    __nv_bfloat162 h = __floats2bfloat162_rn(fmaxf(v0, 0.f), fmaxf(v1, 0.f));
    return *(uint32_t*)&h;
}
__device__ __forceinline__ uint32_t pack2(float v0, float v1) {
    __nv_bfloat162 h = __floats2bfloat162_rn(v0, v1);
    return *(uint32_t*)&h;
}
__device__ __forceinline__ uint32_t bpair(const uint16_t* P, const uint16_t* Q,
                                          int k, float tv) {
    uint32_t pu = __ldg((const uint32_t*)(P + k));
    uint32_t qu = __ldg((const uint32_t*)(Q + k));
    float2 p2 = __bfloat1622float2(*(__nv_bfloat162*)&pu);
    float2 q2 = __bfloat1622float2(*(__nv_bfloat162*)&qu);
    return pack2(fmaxf(fmaf(tv, p2.x, q2.x), 0.f), fmaxf(fmaf(tv, p2.y, q2.y), 0.f));
}

template<int NT, int BLD>
__device__ __forceinline__ void gemm_chain(const uint32_t af[7][4], const uint16_t* wS,
                                           int l16, int lh, float acc[NT][4])
{
    #pragma unroll
    for (int nt = 0; nt < NT; nt++)
        #pragma unroll
        for (int i = 0; i < 4; i++) acc[nt][i] = 0.f;
    #pragma unroll
    for (int kk = 0; kk < 7; kk++) {
        const uint16_t* wrow = wS + (kk * 16 + l16) * BLD + 8 * lh;
        #pragma unroll
        for (int np = 0; np < NT / 2; np++) {
            uint32_t r0, r1, r2, r3;
            ldm_x4_t(smem_u32(wrow + np * 16), r0, r1, r2, r3);
            mma_bf16(acc[2 * np],     af[kk][0], af[kk][1], af[kk][2], af[kk][3], r0, r1);
            mma_bf16(acc[2 * np + 1], af[kk][0], af[kk][1], af[kk][2], af[kk][3], r2, r3);
        }
    }
}
__device__ __forceinline__ void repack(const float acc[14][4], uint32_t af[7][4])
{
    #pragma unroll
    for (int j = 0; j < 7; j++) {
        af[j][0] = pack_relu2(acc[2 * j][0],     acc[2 * j][1]);
        af[j][1] = pack_relu2(acc[2 * j][2],     acc[2 * j][3]);
        af[j][2] = pack_relu2(acc[2 * j + 1][0], acc[2 * j + 1][1]);
        af[j][3] = pack_relu2(acc[2 * j + 1][2], acc[2 * j + 1][3]);
    }
}

// ---------------- pack: pad prep weights to bf16 [k][LD] + zero F ----------------
__global__ void pack_prep(const float* __restrict__ W1, const float* __restrict__ W2,
                          const float* __restrict__ W3, const float* __restrict__ U1)
{
    int i = blockIdx.x * blockDim.x + threadIdx.x;
    int which = blockIdx.y;
    if (which == 0) {
        if (i < W1P_N) {
            int k = i / PBLD, n = i - k * PBLD;
            float v = (k < 128 && n < 200) ? __ldg(W1 + k * 200 + n) : 0.f;
            __nv_bfloat16 h = __float2bfloat16(v);
            g_W1p[i] = *(uint16_t*)&h;
        }
    } else if (which == 1) {
        if (i < W2P_N) {
            int k = i / PBLD, n = i - k * PBLD;
            float v = (k < 200 && n < 200) ? __ldg(W2 + k * 200 + n) : 0.f;
            __nv_bfloat16 h = __float2bfloat16(v);
            g_W2p[i] = *(uint16_t*)&h;
        }
    } else if (which == 2) {
        if (i < W3P_N) {
            int k = i / P3LD, n = i - k * P3LD;
            float v = (k < 200 && n < C_SZ) ? __ldg(W3 + k * C_SZ + n) : 0.f;
            __nv_bfloat16 h = __float2bfloat16(v);
            g_W3p[i] = *(uint16_t*)&h;
        }
    } else if (which == 3) {
        if (i < U1PP_N) {
            int k = i / PULD, n = i - k * PULD;
            float v = (k < 128 && n < HU) ? __ldg(U1 + k * HU + n) : 0.f;
            __nv_bfloat16 h = __float2bfloat16(v);
            g_U1Pp[i] = *(uint16_t*)&h;
        }
    } else if (which == 4) {
        if (i < U1QP_N) {
            int k = i / PULD, n = i - k * PULD;
            float v = (k < 64 && n < HU) ? __ldg(U1 + (D_SZ + k) * HU + n) : 0.f;
            __nv_bfloat16 h = __float2bfloat16(v);
            g_U1Qp[i] = *(uint16_t*)&h;
        }
    } else {
        if (i < B_SZ) g_F[i] = 0.f;
    }
}

// ---------------- prep v7: tensor-core prep, 128 CTAs x 16 rows ----------------
__device__ __forceinline__ void cpy16(const uint16_t* g, uint16_t* s, int n16, int tid) {
    const uint4* src = (const uint4*)g;
    uint4* dst = (uint4*)s;
    for (int i = tid; i < n16 / 8; i += 128) dst[i] = src[i];
}

// generic layer: af (K16 k-steps) x W[k][BLD] -> act out (relu + bias)
template<int K16>
__device__ __forceinline__ void layer_mma(const uint32_t af[][4], const uint16_t* wS,
                                          int BLD, int npairs, int nw, int l16, int lh,
                                          int tg, int qrow, const float* bias, int nreal,
                                          uint16_t* outAct, int outLD)
{
    for (int p = nw; p < npairs; p += 4) {
        float acc[2][4] = {};
        #pragma unroll
        for (int kk = 0; kk < K16; kk++) {
            uint32_t r0, r1, r2, r3;
            ldm_x4_t(smem_u32(wS + (kk * 16 + l16) * BLD + p * 16 + 8 * lh),
                     r0, r1, r2, r3);
            mma_bf16(acc[0], af[kk][0], af[kk][1], af[kk][2], af[kk][3], r0, r1);
            mma_bf16(acc[1], af[kk][0], af[kk][1], af[kk][2], af[kk][3], r2, r3);
        }
        #pragma unroll
        for (int t = 0; t < 2; t++) {
            int c = p * 16 + t * 8 + tg * 2;
            float b0 = (c < nreal)     ? __ldg(bias + c)     : 0.f;
            float b1 = (c + 1 < nreal) ? __ldg(bias + c + 1) : 0.f;
            *(uint32_t*)(outAct + qrow * outLD + c) =
                pack_relu2(acc[t][0] + b0, acc[t][1] + b1);
            *(uint32_t*)(outAct + (qrow + 8) * outLD + c) =
                pack_relu2(acc[t][2] + b0, acc[t][3] + b1);
        }
    }
}

template<int K16>
__device__ __forceinline__ void build_af(uint32_t af[][4], const uint16_t* act,
                                         int LD, int tg, int qrow)
{
    #pragma unroll
    for (int j = 0; j < K16; j++) {
        int k0 = j * 16 + tg * 2;
        af[j][0] = *(const uint32_t*)(act + qrow * LD + k0);
        af[j][1] = *(const uint32_t*)(act + (qrow + 8) * LD + k0);
        af[j][2] = *(const uint32_t*)(act + qrow * LD + k0 + 8);
        af[j][3] = *(const uint32_t*)(act + (qrow + 8) * LD + k0 + 8);
    }
}

__global__ void __launch_bounds__(128, 1)
prep_tensor(const float* __restrict__ x,
            const float* __restrict__ b1, const float* __restrict__ b2,
            const float* __restrict__ b3, const float* __restrict__ c1)
{
    extern __shared__ __align__(16) uint16_t ps[];
    uint16_t* Wbuf = ps;                    // W2P_N b16 (largest stage)
    uint16_t* act1 = ps + W2P_N;            // 16 * PBLD
    uint16_t* act2 = act1 + 16 * PBLD;

    int tid = threadIdx.x;
    int lane = tid & 31, nw = tid >> 5;
    int tg = lane & 3, qrow = lane >> 2;
    int l16 = lane & 15, lh = lane >> 4;
    int m0 = blockIdx.x * 16;

    // ---- stage 1: W1 ----
    cpy16(g_W1p, Wbuf, W1P_N, tid);
    __syncthreads();

    uint32_t afx[8][4];
    {   // A-fragments of x (fp32 -> bf16)
        const float* xA = x + (m0 + qrow) * D_SZ;
        const float* xB = xA + 8 * D_SZ;
        #pragma unroll
        for (int j = 0; j < 8; j++) {
            int k0 = j * 16 + tg * 2;
            float2 a0 = *(const float2*)(xA + k0);
            float2 a1 = *(const float2*)(xB + k0);
            float2 a2 = *(const float2*)(xA + k0 + 8);
            float2 a3 = *(const float2*)(xB + k0 + 8);
            afx[j][0] = pack2(a0.x, a0.y);
            afx[j][1] = pack2(a1.x, a1.y);
            afx[j][2] = pack2(a2.x, a2.y);
            afx[j][3] = pack2(a3.x, a3.y);
        }
    }
    layer_mma<8>(afx, Wbuf, PBLD, 13, nw, l16, lh, tg, qrow, b1, 200, act1, PBLD);
    __syncthreads();

    // ---- stage 2: W2 ----
    cpy16(g_W2p, Wbuf, W2P_N, tid);
    __syncthreads();
    uint32_t af2[13][4];
    build_af<13>(af2, act1, PBLD, tg, qrow);
    layer_mma<13>(af2, Wbuf, PBLD, 13, nw, l16, lh, tg, qrow, b2, 200, act2, PBLD);
    __syncthreads();

    // ---- stage 3: W3 + U1P + U1Q ----
    cpy16(g_W3p,  Wbuf,                 W3P_N,  tid);
    cpy16(g_U1Pp, Wbuf + W3P_N,         U1PP_N, tid);
    cpy16(g_U1Qp, Wbuf + W3P_N + U1PP_N, U1QP_N, tid);
    __syncthreads();

    uint32_t af3[13][4];
    build_af<13>(af3, act2, PBLD, tg, qrow);
    // L3 -> h into act1 (N=64 -> 4 pairs, one per warp)
    layer_mma<13>(af3, Wbuf, P3LD, 4, nw, l16, lh, tg, qrow, b3, C_SZ, act1, PBLD);

    // P = x @ U1[:128] (no bias/relu) -> g_Pb  (7 pairs, N=112 incl pad)
    {
        const uint16_t* Up = Wbuf + W3P_N;
        for (int p = nw; p < 7; p += 4) {
            float acc[2][4] = {};
            #pragma unroll
            for (int kk = 0; kk < 8; kk++) {
                uint32_t r0, r1, r2, r3;
                ldm_x4_t(smem_u32(Up + (kk * 16 + l16) * PULD + p * 16 + 8 * lh),
                         r0, r1, r2, r3);
                mma_bf16(acc[0], afx[kk][0], afx[kk][1], afx[kk][2], afx[kk][3], r0, r1);
                mma_bf16(acc[1], afx[kk][0], afx[kk][1], afx[kk][2], afx[kk][3], r2, r3);
            }
            #pragma unroll
            for (int t = 0; t < 2; t++) {
                int c = p * 16 + t * 8 + tg * 2;
                *(uint32_t*)((uint16_t*)g_Pb + (m0 + qrow) * KP + c) =
                    pack2(acc[t][0], acc[t][1]);
                *(uint32_t*)((uint16_t*)g_Pb + (m0 + qrow + 8) * KP + c) =
                    pack2(acc[t][2], acc[t][3]);
            }
        }
    }
    __syncthreads();   // h (act1) ready

    // Q = h @ U1[128:] + c1 (col100 = 1.0 bias lane) -> g_Qb
    {
        const uint16_t* Uq = Wbuf + W3P_N + U1PP_N;
        uint32_t afq[4][4];
        build_af<4>(afq, act1, PBLD, tg, qrow);
        for (int p = nw; p < 7; p += 4) {
            float acc[2][4] = {};
            #pragma unroll
            for (int kk = 0; kk < 4; kk++) {
                uint32_t r0, r1, r2, r3;
                ldm_x4_t(smem_u32(Uq + (kk * 16 + l16) * PULD + p * 16 + 8 * lh),
                         r0, r1, r2, r3);
                mma_bf16(acc[0], afq[kk][0], afq[kk][1], afq[kk][2], afq[kk][3], r0, r1);
                mma_bf16(acc[1], afq[kk][0], afq[kk][1], afq[kk][2], afq[kk][3], r2, r3);
            }
            #pragma unroll
            for (int t = 0; t < 2; t++) {
                int c = p * 16 + t * 8 + tg * 2;
                float q0 = (c < HU) ? __ldg(c1 + c)
                                    : ((c == BIAS_K) ? 1.0f : 0.f);
                float q1 = (c + 1 < HU) ? __ldg(c1 + c + 1)
                                        : ((c + 1 == BIAS_K) ? 1.0f : 0.f);
                *(uint32_t*)((uint16_t*)g_Qb + (m0 + qrow) * KP + c) =
                    pack2(acc[t][0] + q0, acc[t][1] + q1);
                *(uint32_t*)((uint16_t*)g_Qb + (m0 + qrow + 8) * KP + c) =
                    pack2(acc[t][2] + q0, acc[t][3] + q1);
            }
        }
    }
}

// ---------------- main: register-chained bf16 mma (R13, unchanged) ---------------
__global__ void __launch_bounds__(NTH, 1)
umnn_main(const float* __restrict__ x,
          const float* __restrict__ U2, const float* __restrict__ c2,
          const float* __restrict__ U3, const float* __restrict__ c3,
          const float* __restrict__ U4, const float* __restrict__ c4)
{
    extern __shared__ __align__(16) uint16_t Wsm[];
    int tid = threadIdx.x;

    for (int i = tid; i < KP * W23_LD; i += NTH) {
        int k = i / W23_LD, n = i - k * W23_LD;
        float a = 0.f, b = 0.f;
        if (k < HU && n < HU) {
            a = __ldg(U2 + k * HU + n);
            b = __ldg(U3 + k * HU + n);
        } else if (k == BIAS_K) {
            if (n < HU)            { a = __ldg(c2 + n); b = __ldg(c3 + n); }
            else if (n == BIAS_K)  { a = 1.0f;          b = 1.0f; }
        }
        __nv_bfloat16 ha = __float2bfloat16(a), hb = __float2bfloat16(b);
        Wsm[W2_OFF + i] = *(uint16_t*)&ha;
        Wsm[W3_OFF + i] = *(uint16_t*)&hb;
    }
    for (int i = tid; i < KP * W4_LD; i += NTH) {
        int k = i / W4_LD, n = i - k * W4_LD;
        float a = 0.f;
        if (k < HU && n < D_SZ)            a = __ldg(U4 + k * D_SZ + n);
        else if (k == BIAS_K && n < D_SZ)  a = __ldg(c4 + n);
        __nv_bfloat16 ha = __float2bfloat16(a);
        Wsm[W4_OFF + i] = *(uint16_t*)&ha;
    }
    __syncthreads();

    const uint16_t* W2s = Wsm + W2_OFF;
    const uint16_t* W3s = Wsm + W3_OFF;
    const uint16_t* W4s = Wsm + W4_OFF;

    int lane = tid & 31, w = tid >> 5;
    int tg = lane & 3, qrow = lane >> 2;
    int l16 = lane & 15, lh = lane >> 4;
    int gw = blockIdx.x * 16 + w;

    for (int chunk = gw; chunk < NCHUNK; chunk += GW_STRIDE) {
        int r0 = chunk * 16;
        int rA = r0 + qrow, rB = rA + 8;
        int bA = rA / T_STEPS, bB = rB / T_STEPS;
        float tA = ((float)(rA - bA * T_STEPS) + 0.5f) * (1.0f / T_STEPS);
        float tB = ((float)(rB - bB * T_STEPS) + 0.5f) * (1.0f / T_STEPS);
        const uint16_t* PA = (const uint16_t*)g_Pb + bA * KP;
        const uint16_t* QA = (const uint16_t*)g_Qb + bA * KP;
        const uint16_t* PB = (const uint16_t*)g_Pb + bB * KP;
        const uint16_t* QB = (const uint16_t*)g_Qb + bB * KP;

        uint32_t af[7][4];
        #pragma unroll
        for (int j = 0; j < 7; j++) {
            int k0 = j * 16 + tg * 2;
            af[j][0] = bpair(PA, QA, k0,     tA);
            af[j][1] = bpair(PB, QB, k0,     tB);
            af[j][2] = bpair(PA, QA, k0 + 8, tA);
            af[j][3] = bpair(PB, QB, k0 + 8, tB);
        }

        float acc[14][4];
        gemm_chain<14, W23_LD>(af, W2s, l16, lh, acc);
        repack(acc, af);
        gemm_chain<14, W23_LD>(af, W3s, l16, lh, acc);
        repack(acc, af);

        float acc4[16][4];
        gemm_chain<16, W4_LD>(af, W4s, l16, lh, acc4);

        const float* xA = x + bA * D_SZ;
        const float* xB = x + bB * D_SZ;
        float sA = 0.f, sB = 0.f;
        #pragma unroll
        for (int nt = 0; nt < 16; nt++) {
            int c = nt * 8 + tg * 2;
            float p0 = acc4[nt][0], p1 = acc4[nt][1];
            float p2 = acc4[nt][2], p3 = acc4[nt][3];
            float f0 = p0 > 0.f ? p0 + 1.f : __expf(p0);
            float f1 = p1 > 0.f ? p1 + 1.f : __expf(p1);
            float f2 = p2 > 0.f ? p2 + 1.f : __expf(p2);
            float f3 = p3 > 0.f ? p3 + 1.f : __expf(p3);
            sA += f0 * __ldg(xA + c) + f1 * __ldg(xA + c + 1);
            sB += f2 * __ldg(xB + c) + f3 * __ldg(xB + c + 1);
        }
        sA += __shfl_xor_sync(0xffffffff, sA, 1);
        sA += __shfl_xor_sync(0xffffffff, sA, 2);
        sB += __shfl_xor_sync(0xffffffff, sB, 1);
        sB += __shfl_xor_sync(0xffffffff, sB, 2);
        if (tg == 0) {
            atomicAdd(&g_F[bA], sA);
            atomicAdd(&g_F[bB], sB);
        }
    }
}

// ---------------- finish: sigmoid(F / T) ----------------
__global__ void finish_kernel(float* __restrict__ out)
{
    int i = blockIdx.x * blockDim.x + threadIdx.x;
    if (i < B_SZ) {
        float F = g_F[i] * (1.0f / T_STEPS);
        out[i] = 1.0f / (1.0f + expf(-F));
    }
}

// ---------------- launch ----------------
extern "C" void kernel_launch(void* const* d_in, const int* in_sizes, int n_in,
                              void* d_out, int out_size)
{
    (void)in_sizes; (void)n_in; (void)out_size;
    const float* x  = (const float*)d_in[0];
    const float* W1 = (const float*)d_in[1];
    const float* b1 = (const float*)d_in[2];
    const float* W2 = (const float*)d_in[3];
    const float* b2 = (const float*)d_in[4];
    const float* W3 = (const float*)d_in[5];
    const float* b3 = (const float*)d_in[6];
    const float* U1 = (const float*)d_in[7];
    const float* c1 = (const float*)d_in[8];
    const float* U2 = (const float*)d_in[9];
    const float* c2 = (const float*)d_in[10];
    const float* U3 = (const float*)d_in[11];
    const float* c3 = (const float*)d_in[12];
    const float* U4 = (const float*)d_in[13];
    const float* c4 = (const float*)d_in[14];
    float* out = (float*)d_out;

    cudaFuncSetAttribute(umnn_main, cudaFuncAttributeMaxDynamicSharedMemorySize, SMEM_MAIN);
    cudaFuncSetAttribute(prep_tensor, cudaFuncAttributeMaxDynamicSharedMemorySize, PREP_SMEM);

    // 1) pack prep weights (bf16 padded) + zero F
    pack_prep<<<dim3(176, 6), 256>>>(W1, W2, W3, U1);
    // 2) tensor-core prep: x -> h -> P,Q (128 CTAs x 16 rows)
    prep_tensor<<<B_SZ / 16, 128, PREP_SMEM>>>(x, b1, b2, b3, c1);
    // 3) register-chained persistent mma main kernel (R13, unchanged)
    umnn_main<<<GRID, NTH, SMEM_MAIN>>>(x, U2, c2, U3, c3, U4, c4);
    // 4) out = sigmoid(F / 300)
    finish_kernel<<<(B_SZ + 255) / 256, 256>>>(out);
}

// round 15
// speedup vs baseline: 1.5178x; 1.0139x over previous
#include <cuda_runtime.h>
#include <cuda_bf16.h>
#include <cstdint>

// ---------------- problem constants ----------------
#define B_SZ     2048
#define D_SZ     128
#define C_SZ     64
#define T_STEPS  300
#define HU       100
#define ROWS_TOTAL (B_SZ * T_STEPS)       // 614400
#define GRID     148
#define NTH      512
#define NCHUNK   (ROWS_TOTAL / 16)        // 38400
#define GW_STRIDE (GRID * 16)

#define KP      112                        // padded hidden; col/row 100 = bias lane
#define BIAS_K  100
#define W23_LD  120
#define W4_LD   136
#define W2_OFF  0
#define W3_OFF  (KP * W23_LD)
#define W4_OFF  (2 * KP * W23_LD)
#define W_TOTAL (2 * KP * W23_LD + KP * W4_LD)   // 42112 b16
#define SMEM_MAIN (W_TOTAL * 2)                  // 84224 B

// prep packed-weight layouts (bf16, [k][LD])
#define PBLD   216
#define P3LD   72
#define PULD   120
#define W1P_N  (128 * PBLD)
#define W2P_N  (208 * PBLD)
#define W3P_N  (208 * P3LD)
#define U1PP_N (128 * PULD)
#define U1QP_N (64 * PULD)
#define PREP_SMEM ((W2P_N + 2 * 16 * PBLD) * 2)

// ---------------- device globals ----------------
__device__ __align__(16) __nv_bfloat16 g_Pb[B_SZ * KP];
__device__ __align__(16) __nv_bfloat16 g_Qb[B_SZ * KP];
__device__ float g_F[B_SZ];
__device__ unsigned int g_done;
__device__ __align__(16) uint16_t g_W1p[W1P_N];
__device__ __align__(16) uint16_t g_W2p[W2P_N];
__device__ __align__(16) uint16_t g_W3p[W3P_N];
__device__ __align__(16) uint16_t g_U1Pp[U1PP_N];
__device__ __align__(16) uint16_t g_U1Qp[U1QP_N];

// ---------------- helpers ----------------
__device__ __forceinline__ uint32_t smem_u32(const void* p) {
    return (uint32_t)__cvta_generic_to_shared(p);
}
__device__ __forceinline__ void ldm_x4_t(uint32_t addr, uint32_t& r0, uint32_t& r1,
                                         uint32_t& r2, uint32_t& r3) {
    asm volatile("ldmatrix.sync.aligned.m8n8.x4.trans.shared.b16 {%0,%1,%2,%3}, [%4];"
                 : "=r"(r0), "=r"(r1), "=r"(r2), "=r"(r3) : "r"(addr));
}
__device__ __forceinline__ void mma_bf16(float c[4], uint32_t a0, uint32_t a1, uint32_t a2,
                                         uint32_t a3, uint32_t b0, uint32_t b1) {
    asm volatile(
        "mma.sync.aligned.m16n8k16.row.col.f32.bf16.bf16.f32 "
        "{%0,%1,%2,%3},{%4,%5,%6,%7},{%8,%9},{%0,%1,%2,%3};"
        : "+f"(c[0]), "+f"(c[1]), "+f"(c[2]), "+f"(c[3])
        : "r"(a0), "r"(a1), "r"(a2), "r"(a3), "r"(b0), "r"(b1));
}
__device__ __forceinline__ uint32_t pack_relu2(float v0, float v1) {
    __nv_bfloat162 h = __floats2bfloat162_rn(fmaxf(v0, 0.f), fmaxf(v1, 0.f));
    return *(uint32_t*)&h;
}
__device__ __forceinline__ uint32_t pack2(float v0, float v1) {
    __nv_bfloat162 h = __floats2bfloat162_rn(v0, v1);
    return *(uint32_t*)&h;
}
__device__ __forceinline__ uint32_t bpair(const uint16_t* P, const uint16_t* Q,
                                          int k, float tv) {
    uint32_t pu = __ldg((const uint32_t*)(P + k));
    uint32_t qu = __ldg((const uint32_t*)(Q + k));
    float2 p2 = __bfloat1622float2(*(__nv_bfloat162*)&pu);
    float2 q2 = __bfloat1622float2(*(__nv_bfloat162*)&qu);
    return pack2(fmaxf(fmaf(tv, p2.x, q2.x), 0.f), fmaxf(fmaf(tv, p2.y, q2.y), 0.f));
}

// 13-tile chained GEMM (cols 0..103): 6 full tile-pairs + half pair (acc[12] only).
template<int BLD>
__device__ __forceinline__ void gemm_chain13(const uint32_t af[7][4], const uint16_t* wS,
                                             int l16, int lh, float acc[13][4])
{
    #pragma unroll
    for (int nt = 0; nt < 13; nt++)
        #pragma unroll
        for (int i = 0; i < 4; i++) acc[nt][i] = 0.f;
    #pragma unroll
    for (int kk = 0; kk < 7; kk++) {
        const uint16_t* wrow = wS + (kk * 16 + l16) * BLD + 8 * lh;
        #pragma unroll
        for (int np = 0; np < 6; np++) {
            uint32_t r0, r1, r2, r3;
            ldm_x4_t(smem_u32(wrow + np * 16), r0, r1, r2, r3);
            mma_bf16(acc[2 * np],     af[kk][0], af[kk][1], af[kk][2], af[kk][3], r0, r1);
            mma_bf16(acc[2 * np + 1], af[kk][0], af[kk][1], af[kk][2], af[kk][3], r2, r3);
        }
        {   // half pair: tile 12 only (cols 96..103; tile 13 weights are zero)
            uint32_t r0, r1, r2, r3;
            ldm_x4_t(smem_u32(wrow + 6 * 16), r0, r1, r2, r3);
            mma_bf16(acc[12], af[kk][0], af[kk][1], af[kk][2], af[kk][3], r0, r1);
        }
    }
}
// full 16-tile chained GEMM (L4)
template<int BLD>
__device__ __forceinline__ void gemm_chain16(const uint32_t af[7][4], const uint16_t* wS,
                                             int l16, int lh, float acc[16][4])
{
    #pragma unroll
    for (int nt = 0; nt < 16; nt++)
        #pragma unroll
        for (int i = 0; i < 4; i++) acc[nt][i] = 0.f;
    #pragma unroll
    for (int kk = 0; kk < 7; kk++) {
        const uint16_t* wrow = wS + (kk * 16 + l16) * BLD + 8 * lh;
        #pragma unroll
        for (int np = 0; np < 8; np++) {
            uint32_t r0, r1, r2, r3;
            ldm_x4_t(smem_u32(wrow + np * 16), r0, r1, r2, r3);
            mma_bf16(acc[2 * np],     af[kk][0], af[kk][1], af[kk][2], af[kk][3], r0, r1);
            mma_bf16(acc[2 * np + 1], af[kk][0], af[kk][1], af[kk][2], af[kk][3], r2, r3);
        }
    }
}
// 13-tile C-fragment -> next A-fragment; af[6][2..3] = 0 (cols 104..111 are zero)
__device__ __forceinline__ void repack13(const float acc[13][4], uint32_t af[7][4])
{
    #pragma unroll
    for (int j = 0; j < 6; j++) {
        af[j][0] = pack_relu2(acc[2 * j][0],     acc[2 * j][1]);
        af[j][1] = pack_relu2(acc[2 * j][2],     acc[2 * j][3]);
        af[j][2] = pack_relu2(acc[2 * j + 1][0], acc[2 * j + 1][1]);
        af[j][3] = pack_relu2(acc[2 * j + 1][2], acc[2 * j + 1][3]);
    }
    af[6][0] = pack_relu2(acc[12][0], acc[12][1]);
    af[6][1] = pack_relu2(acc[12][2], acc[12][3]);
    af[6][2] = 0u;
    af[6][3] = 0u;
}

// ---------------- pack: pad prep weights to bf16 [k][LD] + zero F + reset ticket ----
__global__ void pack_prep(const float* __restrict__ W1, const float* __restrict__ W2,
                          const float* __restrict__ W3, const float* __restrict__ U1)
{
    int i = blockIdx.x * blockDim.x + threadIdx.x;
    int which = blockIdx.y;
    if (which == 0) {
        if (i < W1P_N) {
            int k = i / PBLD, n = i - k * PBLD;
            float v = (k < 128 && n < 200) ? __ldg(W1 + k * 200 + n) : 0.f;
            __nv_bfloat16 h = __float2bfloat16(v);
            g_W1p[i] = *(uint16_t*)&h;
        }
    } else if (which == 1) {
        if (i < W2P_N) {
            int k = i / PBLD, n = i - k * PBLD;
            float v = (k < 200 && n < 200) ? __ldg(W2 + k * 200 + n) : 0.f;
            __nv_bfloat16 h = __float2bfloat16(v);
            g_W2p[i] = *(uint16_t*)&h;
        }
    } else if (which == 2) {
        if (i < W3P_N) {
            int k = i / P3LD, n = i - k * P3LD;
            float v = (k < 200 && n < C_SZ) ? __ldg(W3 + k * C_SZ + n) : 0.f;
            __nv_bfloat16 h = __float2bfloat16(v);
            g_W3p[i] = *(uint16_t*)&h;
        }
    } else if (which == 3) {
        if (i < U1PP_N) {
            int k = i / PULD, n = i - k * PULD;
            float v = (k < 128 && n < HU) ? __ldg(U1 + k * HU + n) : 0.f;
            __nv_bfloat16 h = __float2bfloat16(v);
            g_U1Pp[i] = *(uint16_t*)&h;
        }
    } else if (which == 4) {
        if (i < U1QP_N) {
            int k = i / PULD, n = i - k * PULD;
            float v = (k < 64 && n < HU) ? __ldg(U1 + (D_SZ + k) * HU + n) : 0.f;
            __nv_bfloat16 h = __float2bfloat16(v);
            g_U1Qp[i] = *(uint16_t*)&h;
        }
    } else {
        if (i < B_SZ) g_F[i] = 0.f;
        if (i == 0) g_done = 0u;
    }
}

// ---------------- prep v7: tensor-core prep, 128 CTAs x 16 rows (R14) -------------
__device__ __forceinline__ void cpy16(const uint16_t* g, uint16_t* s, int n16, int tid) {
    const uint4* src = (const uint4*)g;
    uint4* dst = (uint4*)s;
    for (int i = tid; i < n16 / 8; i += 128) dst[i] = src[i];
}

template<int K16>
__device__ __forceinline__ void layer_mma(const uint32_t af[][4], const uint16_t* wS,
                                          int BLD, int npairs, int nw, int l16, int lh,
                                          int tg, int qrow, const float* bias, int nreal,
                                          uint16_t* outAct, int outLD)
{
    for (int p = nw; p < npairs; p += 4) {
        float acc[2][4] = {};
        #pragma unroll
        for (int kk = 0; kk < K16; kk++) {
            uint32_t r0, r1, r2, r3;
            ldm_x4_t(smem_u32(wS + (kk * 16 + l16) * BLD + p * 16 + 8 * lh),
                     r0, r1, r2, r3);
            mma_bf16(acc[0], af[kk][0], af[kk][1], af[kk][2], af[kk][3], r0, r1);
            mma_bf16(acc[1], af[kk][0], af[kk][1], af[kk][2], af[kk][3], r2, r3);
        }
        #pragma unroll
        for (int t = 0; t < 2; t++) {
            int c = p * 16 + t * 8 + tg * 2;
            float b0 = (c < nreal)     ? __ldg(bias + c)     : 0.f;
            float b1 = (c + 1 < nreal) ? __ldg(bias + c + 1) : 0.f;
            *(uint32_t*)(outAct + qrow * outLD + c) =
                pack_relu2(acc[t][0] + b0, acc[t][1] + b1);
            *(uint32_t*)(outAct + (qrow + 8) * outLD + c) =
                pack_relu2(acc[t][2] + b0, acc[t][3] + b1);
        }
    }
}

template<int K16>
__device__ __forceinline__ void build_af(uint32_t af[][4], const uint16_t* act,
                                         int LD, int tg, int qrow)
{
    #pragma unroll
    for (int j = 0; j < K16; j++) {
        int k0 = j * 16 + tg * 2;
        af[j][0] = *(const uint32_t*)(act + qrow * LD + k0);
        af[j][1] = *(const uint32_t*)(act + (qrow + 8) * LD + k0);
        af[j][2] = *(const uint32_t*)(act + qrow * LD + k0 + 8);
        af[j][3] = *(const uint32_t*)(act + (qrow + 8) * LD + k0 + 8);
    }
}

__global__ void __launch_bounds__(128, 1)
prep_tensor(const float* __restrict__ x,
            const float* __restrict__ b1, const float* __restrict__ b2,
            const float* __restrict__ b3, const float* __restrict__ c1)
{
    extern __shared__ __align__(16) uint16_t ps[];
    uint16_t* Wbuf = ps;
    uint16_t* act1 = ps + W2P_N;
    uint16_t* act2 = act1 + 16 * PBLD;

    int tid = threadIdx.x;
    int lane = tid & 31, nw = tid >> 5;
    int tg = lane & 3, qrow = lane >> 2;
    int l16 = lane & 15, lh = lane >> 4;
    int m0 = blockIdx.x * 16;

    cpy16(g_W1p, Wbuf, W1P_N, tid);
    __syncthreads();

    uint32_t afx[8][4];
    {
        const float* xA = x + (m0 + qrow) * D_SZ;
        const float* xB = xA + 8 * D_SZ;
        #pragma unroll
        for (int j = 0; j < 8; j++) {
            int k0 = j * 16 + tg * 2;
            float2 a0 = *(const float2*)(xA + k0);
            float2 a1 = *(const float2*)(xB + k0);
            float2 a2 = *(const float2*)(xA + k0 + 8);
            float2 a3 = *(const float2*)(xB + k0 + 8);
            afx[j][0] = pack2(a0.x, a0.y);
            afx[j][1] = pack2(a1.x, a1.y);
            afx[j][2] = pack2(a2.x, a2.y);
            afx[j][3] = pack2(a3.x, a3.y);
        }
    }
    layer_mma<8>(afx, Wbuf, PBLD, 13, nw, l16, lh, tg, qrow, b1, 200, act1, PBLD);
    __syncthreads();

    cpy16(g_W2p, Wbuf, W2P_N, tid);
    __syncthreads();
    uint32_t af2[13][4];
    build_af<13>(af2, act1, PBLD, tg, qrow);
    layer_mma<13>(af2, Wbuf, PBLD, 13, nw, l16, lh, tg, qrow, b2, 200, act2, PBLD);
    __syncthreads();

    cpy16(g_W3p,  Wbuf,                  W3P_N,  tid);
    cpy16(g_U1Pp, Wbuf + W3P_N,          U1PP_N, tid);
    cpy16(g_U1Qp, Wbuf + W3P_N + U1PP_N, U1QP_N, tid);
    __syncthreads();

    uint32_t af3[13][4];
    build_af<13>(af3, act2, PBLD, tg, qrow);
    layer_mma<13>(af3, Wbuf, P3LD, 4, nw, l16, lh, tg, qrow, b3, C_SZ, act1, PBLD);

    {
        const uint16_t* Up = Wbuf + W3P_N;
        for (int p = nw; p < 7; p += 4) {
            float acc[2][4] = {};
            #pragma unroll
            for (int kk = 0; kk < 8; kk++) {
                uint32_t r0, r1, r2, r3;
                ldm_x4_t(smem_u32(Up + (kk * 16 + l16) * PULD + p * 16 + 8 * lh),
                         r0, r1, r2, r3);
                mma_bf16(acc[0], afx[kk][0], afx[kk][1], afx[kk][2], afx[kk][3], r0, r1);
                mma_bf16(acc[1], afx[kk][0], afx[kk][1], afx[kk][2], afx[kk][3], r2, r3);
            }
            #pragma unroll
            for (int t = 0; t < 2; t++) {
                int c = p * 16 + t * 8 + tg * 2;
                *(uint32_t*)((uint16_t*)g_Pb + (m0 + qrow) * KP + c) =
                    pack2(acc[t][0], acc[t][1]);
                *(uint32_t*)((uint16_t*)g_Pb + (m0 + qrow + 8) * KP + c) =
                    pack2(acc[t][2], acc[t][3]);
            }
        }
    }
    __syncthreads();

    {
        const uint16_t* Uq = Wbuf + W3P_N + U1PP_N;
        uint32_t afq[4][4];
        build_af<4>(afq, act1, PBLD, tg, qrow);
        for (int p = nw; p < 7; p += 4) {
            float acc[2][4] = {};
            #pragma unroll
            for (int kk = 0; kk < 4; kk++) {
                uint32_t r0, r1, r2, r3;
                ldm_x4_t(smem_u32(Uq + (kk * 16 + l16) * PULD + p * 16 + 8 * lh),
                         r0, r1, r2, r3);
                mma_bf16(acc[0], afq[kk][0], afq[kk][1], afq[kk][2], afq[kk][3], r0, r1);
                mma_bf16(acc[1], afq[kk][0], afq[kk][1], afq[kk][2], afq[kk][3], r2, r3);
            }
            #pragma unroll
            for (int t = 0; t < 2; t++) {
                int c = p * 16 + t * 8 + tg * 2;
                float q0 = (c < HU) ? __ldg(c1 + c)
                                    : ((c == BIAS_K) ? 1.0f : 0.f);
                float q1 = (c + 1 < HU) ? __ldg(c1 + c + 1)
                                        : ((c + 1 == BIAS_K) ? 1.0f : 0.f);
                *(uint32_t*)((uint16_t*)g_Qb + (m0 + qrow) * KP + c) =
                    pack2(acc[t][0] + q0, acc[t][1] + q1);
                *(uint32_t*)((uint16_t*)g_Qb + (m0 + qrow + 8) * KP + c) =
                    pack2(acc[t][2] + q0, acc[t][3] + q1);
            }
        }
    }
}

// ---------------- main: register-chained mma + fused finish ----------------
__global__ void __launch_bounds__(NTH, 1)
umnn_main(const float* __restrict__ x,
          const float* __restrict__ U2, const float* __restrict__ c2,
          const float* __restrict__ U3, const float* __restrict__ c3,
          const float* __restrict__ U4, const float* __restrict__ c4,
          float* __restrict__ out)
{
    extern __shared__ __align__(16) uint16_t Wsm[];
    __shared__ unsigned int slast;
    int tid = threadIdx.x;

    for (int i = tid; i < KP * W23_LD; i += NTH) {
        int k = i / W23_LD, n = i - k * W23_LD;
        float a = 0.f, b = 0.f;
        if (k < HU && n < HU) {
            a = __ldg(U2 + k * HU + n);
            b = __ldg(U3 + k * HU + n);
        } else if (k == BIAS_K) {
            if (n < HU)            { a = __ldg(c2 + n); b = __ldg(c3 + n); }
            else if (n == BIAS_K)  { a = 1.0f;          b = 1.0f; }
        }
        __nv_bfloat16 ha = __float2bfloat16(a), hb = __float2bfloat16(b);
        Wsm[W2_OFF + i] = *(uint16_t*)&ha;
        Wsm[W3_OFF + i] = *(uint16_t*)&hb;
    }
    for (int i = tid; i < KP * W4_LD; i += NTH) {
        int k = i / W4_LD, n = i - k * W4_LD;
        float a = 0.f;
        if (k < HU && n < D_SZ)            a = __ldg(U4 + k * D_SZ + n);
        else if (k == BIAS_K && n < D_SZ)  a = __ldg(c4 + n);
        __nv_bfloat16 ha = __float2bfloat16(a);
        Wsm[W4_OFF + i] = *(uint16_t*)&ha;
    }
    __syncthreads();

    const uint16_t* W2s = Wsm + W2_OFF;
    const uint16_t* W3s = Wsm + W3_OFF;
    const uint16_t* W4s = Wsm + W4_OFF;

    int lane = tid & 31, w = tid >> 5;
    int tg = lane & 3, qrow = lane >> 2;
    int l16 = lane & 15, lh = lane >> 4;
    int gw = blockIdx.x * 16 + w;

    for (int chunk = gw; chunk < NCHUNK; chunk += GW_STRIDE) {
        int r0 = chunk * 16;
        int rA = r0 + qrow, rB = rA + 8;
        int bA = rA / T_STEPS, bB = rB / T_STEPS;
        float tA = ((float)(rA - bA * T_STEPS) + 0.5f) * (1.0f / T_STEPS);
        float tB = ((float)(rB - bB * T_STEPS) + 0.5f) * (1.0f / T_STEPS);
        const uint16_t* PA = (const uint16_t*)g_Pb + bA * KP;
        const uint16_t* QA = (const uint16_t*)g_Qb + bA * KP;
        const uint16_t* PB = (const uint16_t*)g_Pb + bB * KP;
        const uint16_t* QB = (const uint16_t*)g_Qb + bB * KP;

        uint32_t af[7][4];
        #pragma unroll
        for (int j = 0; j < 7; j++) {
            int k0 = j * 16 + tg * 2;
            af[j][0] = bpair(PA, QA, k0,     tA);
            af[j][1] = bpair(PB, QB, k0,     tB);
            af[j][2] = bpair(PA, QA, k0 + 8, tA);
            af[j][3] = bpair(PB, QB, k0 + 8, tB);
        }

        float acc[13][4];
        gemm_chain13<W23_LD>(af, W2s, l16, lh, acc);
        repack13(acc, af);
        gemm_chain13<W23_LD>(af, W3s, l16, lh, acc);
        repack13(acc, af);

        float acc4[16][4];
        gemm_chain16<W4_LD>(af, W4s, l16, lh, acc4);

        const float* xA = x + bA * D_SZ;
        const float* xB = x + bB * D_SZ;
        float sA = 0.f, sB = 0.f;
        #pragma unroll
        for (int nt = 0; nt < 16; nt++) {
            int c = nt * 8 + tg * 2;
            float p0 = acc4[nt][0], p1 = acc4[nt][1];
            float p2 = acc4[nt][2], p3 = acc4[nt][3];
            float f0 = p0 > 0.f ? p0 + 1.f : __expf(p0);
            float f1 = p1 > 0.f ? p1 + 1.f : __expf(p1);
            float f2 = p2 > 0.f ? p2 + 1.f : __expf(p2);
            float f3 = p3 > 0.f ? p3 + 1.f : __expf(p3);
            sA += f0 * __ldg(xA + c) + f1 * __ldg(xA + c + 1);
            sB += f2 * __ldg(xB + c) + f3 * __ldg(xB + c + 1);
        }
        sA += __shfl_xor_sync(0xffffffff, sA, 1);
        sA += __shfl_xor_sync(0xffffffff, sA, 2);
        sB += __shfl_xor_sync(0xffffffff, sB, 1);
        sB += __shfl_xor_sync(0xffffffff, sB, 2);
        if (tg == 0) {
            atomicAdd(&g_F[bA], sA);
            atomicAdd(&g_F[bB], sB);
        }
    }

    // fused finish: last CTA to retire computes sigmoid(F/300) -> out
    __syncthreads();
    if (tid == 0) {
        __threadfence();
        unsigned int o = atomicAdd(&g_done, 1u);
        slast = (o == GRID - 1u) ? 1u : 0u;
    }
    __syncthreads();
    if (slast) {
        __threadfence();
        for (int i = tid; i < B_SZ; i += NTH) {
            float F = g_F[i] * (1.0f / T_STEPS);
            out[i] = 1.0f / (1.0f + expf(-F));
        }
    }
}

// ---------------- launch ----------------
extern "C" void kernel_launch(void* const* d_in, const int* in_sizes, int n_in,
                              void* d_out, int out_size)
{
    (void)in_sizes; (void)n_in; (void)out_size;
    const float* x  = (const float*)d_in[0];
    const float* W1 = (const float*)d_in[1];
    const float* b1 = (const float*)d_in[2];
    const float* W2 = (const float*)d_in[3];
    const float* b2 = (const float*)d_in[4];
    const float* W3 = (const float*)d_in[5];
    const float* b3 = (const float*)d_in[6];
    const float* U1 = (const float*)d_in[7];
    const float* c1 = (const float*)d_in[8];
    const float* U2 = (const float*)d_in[9];
    const float* c2 = (const float*)d_in[10];
    const float* U3 = (const float*)d_in[11];
    const float* c3 = (const float*)d_in[12];
    const float* U4 = (const float*)d_in[13];
    const float* c4 = (const float*)d_in[14];
    float* out = (float*)d_out;

    cudaFuncSetAttribute(umnn_main, cudaFuncAttributeMaxDynamicSharedMemorySize, SMEM_MAIN);
    cudaFuncSetAttribute(prep_tensor, cudaFuncAttributeMaxDynamicSharedMemorySize, PREP_SMEM);

    // 1) pack prep weights + zero F + reset done-ticket
    pack_prep<<<dim3(176, 6), 256>>>(W1, W2, W3, U1);
    // 2) tensor-core prep: x -> h -> P,Q
    prep_tensor<<<B_SZ / 16, 128, PREP_SMEM>>>(x, b1, b2, b3, c1);
    // 3) register-chained persistent mma main kernel + fused finish
    umnn_main<<<GRID, NTH, SMEM_MAIN>>>(x, U2, c2, U3, c3, U4, c4, out);
}